// round 1
// baseline (speedup 1.0000x reference)
#include <cuda_runtime.h>

#define RDIM 512
#define CDIM 32
#define NPLANE 3
#define PLANE_ELEMS (RDIM * RDIM * CDIM)   // 8,388,608 floats per plane

// 96 MB scratch: clipped triplane in [plane][y][x][channel] layout.
// Pixel block = 32 floats = 128 B = exactly one L2 line, 128B-aligned.
__device__ float g_planes[NPLANE * PLANE_ELEMS];

// ---------------------------------------------------------------------------
// Kernel 1: transpose [p][c][y][x] -> [p][y][x][c] with clip to [-1, 1].
// One block = one (p, y, 32-wide x tile); 256 threads; smem 32x33 tile.
// Reads: 128B coalesced per c-row. Writes: 128B coalesced per pixel.
// ---------------------------------------------------------------------------
__global__ void transpose_clip_kernel(const float* __restrict__ src) {
    __shared__ float tile[CDIM][33];   // +1 pad: conflict-free column reads

    int bid   = blockIdx.x;
    int xbase = (bid & 15) << 5;       // 16 x-tiles of 32
    int y     = (bid >> 4) & (RDIM - 1);
    int p     = bid >> 13;             // 16 * 512 = 8192 blocks per plane

    int t  = threadIdx.x;
    int lx = t & 31;
    int tc = t >> 5;                   // 0..7 (warp id within block)

    const float* s = src + (p * CDIM) * (RDIM * RDIM) + y * RDIM + xbase;
    #pragma unroll
    for (int i = 0; i < 4; i++) {
        int c = tc + i * 8;            // c constant per warp -> coalesced read
        tile[c][lx] = s[c * (RDIM * RDIM) + lx];
    }
    __syncthreads();

    float* d = g_planes + ((p * RDIM + y) * RDIM + xbase) * CDIM;
    #pragma unroll
    for (int i = 0; i < 4; i++) {
        int xl = tc + i * 8;           // pixel within tile (constant per warp)
        float v = tile[lx][xl];        // lx = channel; stride-33 -> no conflicts
        v = fminf(fmaxf(v, -1.0f), 1.0f);
        d[xl * CDIM + lx] = v;         // consecutive lx -> 128B coalesced write
    }
}

// ---------------------------------------------------------------------------
// Kernel 2: bilinear triplane sampling. 8 lanes per point; lane g owns
// channels [4g, 4g+4). Each tap = one LDG.128; lanes 8k..8k+7 of a warp hit
// the same 128B pixel line -> 4 wavefronts per LDG instruction (minimum).
// Plane (u=col-source, v=row-source) pairs from inv(PLANE_AXES):
//   p0: (cy, cx)   p1: (cz, cx)   p2: (cy, cz)
// ---------------------------------------------------------------------------
__global__ void __launch_bounds__(256) sample_kernel(
    const float* __restrict__ coords, float* __restrict__ out, int M)
{
    int tid = blockIdx.x * blockDim.x + threadIdx.x;
    int pt  = tid >> 3;
    if (pt >= M) return;
    int g   = tid & 7;

    float cx = __ldg(coords + pt * 3 + 0);
    float cy = __ldg(coords + pt * 3 + 1);
    float cz = __ldg(coords + pt * 3 + 2);

    const float4* pl = reinterpret_cast<const float4*>(g_planes);

    float u[3] = {cy, cz, cy};   // -> x (last axis / column)
    float v[3] = {cx, cx, cz};   // -> y (middle axis / row)

    float a0 = 0.f, a1 = 0.f, a2 = 0.f, a3 = 0.f;

    #pragma unroll
    for (int p = 0; p < NPLANE; p++) {
        float sx = (u[p] + 1.0f) * (0.5f * (RDIM - 1));  // align_corners=True
        float sy = (v[p] + 1.0f) * (0.5f * (RDIM - 1));
        float fx = floorf(sx), fy = floorf(sy);
        int   x0 = (int)fx,    y0 = (int)fy;
        float wx1 = sx - fx,   wy1 = sy - fy;
        float wx0 = 1.0f - wx1, wy0 = 1.0f - wy1;

        // coords are in (-1,1) so all 4 taps are in-bounds; clamp is free safety.
        x0 = max(min(x0, RDIM - 1), 0);
        y0 = max(min(y0, RDIM - 1), 0);
        int x1 = min(x0 + 1, RDIM - 1);
        int y1 = min(y0 + 1, RDIM - 1);

        int base = p * (RDIM * RDIM * (CDIM / 4));       // float4 units
        int r0 = base + y0 * (RDIM * (CDIM / 4)) + g;
        int r1 = base + y1 * (RDIM * (CDIM / 4)) + g;

        float4 t00 = __ldg(pl + r0 + x0 * (CDIM / 4));
        float4 t10 = __ldg(pl + r0 + x1 * (CDIM / 4));
        float4 t01 = __ldg(pl + r1 + x0 * (CDIM / 4));
        float4 t11 = __ldg(pl + r1 + x1 * (CDIM / 4));

        float w00 = wx0 * wy0, w10 = wx1 * wy0;
        float w01 = wx0 * wy1, w11 = wx1 * wy1;

        a0 += w00 * t00.x + w10 * t10.x + w01 * t01.x + w11 * t11.x;
        a1 += w00 * t00.y + w10 * t10.y + w01 * t01.y + w11 * t11.y;
        a2 += w00 * t00.z + w10 * t10.z + w01 * t01.z + w11 * t11.z;
        a3 += w00 * t00.w + w10 * t10.w + w01 * t01.w + w11 * t11.w;
    }

    // Out row = 128B; lanes 8k..8k+7 fill one line -> fully coalesced STG.128.
    float4 o = make_float4(a0, a1, a2, a3);
    reinterpret_cast<float4*>(out)[pt * (CDIM / 4) + g] = o;
}

// ---------------------------------------------------------------------------
extern "C" void kernel_launch(void* const* d_in, const int* in_sizes, int n_in,
                              void* d_out, int out_size) {
    const float* coords   = (const float*)d_in[0];
    const float* triplane = (const float*)d_in[1];
    float*       out      = (float*)d_out;
    int M = in_sizes[0] / 3;

    transpose_clip_kernel<<<NPLANE * RDIM * (RDIM / 32), 256>>>(triplane);

    int threads = M * 8;
    sample_kernel<<<(threads + 255) / 256, 256>>>(coords, out, M);
}

// round 2
// speedup vs baseline: 1.5125x; 1.5125x over previous
#include <cuda_runtime.h>
#include <cuda_fp16.h>

#define RDIM 512
#define CDIM 32
#define NPLANE 3
#define PLANE_ELEMS (RDIM * RDIM * CDIM)   // 8,388,608 elems per plane

// 48 MB scratch: clipped triplane as fp16 in [plane][y][x][channel] layout.
// Pixel block = 32 halves = 64 B, 64B-aligned -> 2 sectors per tap.
__device__ __half g_planes[NPLANE * PLANE_ELEMS];

// ---------------------------------------------------------------------------
// Kernel 1: transpose [p][c][y][x] -> [p][y][x][c], clip to [-1,1], fp32->fp16.
// One block = one (p, y, 32-wide x tile); 256 threads; smem 32x33 tile.
// ---------------------------------------------------------------------------
__global__ void transpose_clip_kernel(const float* __restrict__ src) {
    __shared__ float tile[CDIM][33];   // +1 pad: conflict-free column reads

    int bid   = blockIdx.x;
    int xbase = (bid & 15) << 5;       // 16 x-tiles of 32
    int y     = (bid >> 4) & (RDIM - 1);
    int p     = bid >> 13;             // 16 * 512 = 8192 blocks per plane

    int t  = threadIdx.x;
    int lx = t & 31;
    int tc = t >> 5;                   // 0..7 (warp id within block)

    const float* s = src + (p * CDIM) * (RDIM * RDIM) + y * RDIM + xbase;
    #pragma unroll
    for (int i = 0; i < 4; i++) {
        int c = tc + i * 8;            // c constant per warp -> coalesced read
        tile[c][lx] = s[c * (RDIM * RDIM) + lx];
    }
    __syncthreads();

    __half* d = g_planes + ((size_t)(p * RDIM + y) * RDIM + xbase) * CDIM;
    #pragma unroll
    for (int i = 0; i < 4; i++) {
        int xl = tc + i * 8;           // pixel within tile (constant per warp)
        float v = tile[lx][xl];        // lx = channel; stride-33 -> no conflicts
        v = fminf(fmaxf(v, -1.0f), 1.0f);
        d[xl * CDIM + lx] = __float2half_rn(v);  // consecutive lx -> coalesced
    }
}

// ---------------------------------------------------------------------------
// Kernel 2: bilinear triplane sampling from fp16 scratch.
// 4 lanes per point; lane g owns channels [8g, 8g+8). Each tap = one LDG.128
// (16 B = 8 fp16); the 4 lanes of a point cover the 64 B pixel block.
// Plane (u=col-source, v=row-source) pairs from inv(PLANE_AXES):
//   p0: (cy, cx)   p1: (cz, cx)   p2: (cy, cz)
// ---------------------------------------------------------------------------
__global__ void __launch_bounds__(256) sample_kernel(
    const float* __restrict__ coords, float* __restrict__ out, int M)
{
    int tid = blockIdx.x * blockDim.x + threadIdx.x;
    int pt  = tid >> 2;
    if (pt >= M) return;
    int g   = tid & 3;

    float cx = __ldg(coords + pt * 3 + 0);
    float cy = __ldg(coords + pt * 3 + 1);
    float cz = __ldg(coords + pt * 3 + 2);

    const uint4* pl = reinterpret_cast<const uint4*>(g_planes);

    float u[3] = {cy, cz, cy};   // -> x (last axis / column)
    float v[3] = {cx, cx, cz};   // -> y (middle axis / row)

    float acc[8];
    #pragma unroll
    for (int k = 0; k < 8; k++) acc[k] = 0.0f;

    #pragma unroll
    for (int p = 0; p < NPLANE; p++) {
        float sx = (u[p] + 1.0f) * (0.5f * (RDIM - 1));  // align_corners=True
        float sy = (v[p] + 1.0f) * (0.5f * (RDIM - 1));
        float fx = floorf(sx), fy = floorf(sy);
        int   x0 = (int)fx,    y0 = (int)fy;
        float wx1 = sx - fx,   wy1 = sy - fy;
        float wx0 = 1.0f - wx1, wy0 = 1.0f - wy1;

        // coords in (-1,1) keep all taps in-bounds; clamp is free safety.
        x0 = max(min(x0, RDIM - 1), 0);
        y0 = max(min(y0, RDIM - 1), 0);
        int x1 = min(x0 + 1, RDIM - 1);
        int y1 = min(y0 + 1, RDIM - 1);

        // uint4 units: pixel = 4 units (64 B); lane g selects its 16 B slice.
        int base = p * (RDIM * RDIM * 4);
        int r0 = base + y0 * (RDIM * 4) + g;
        int r1 = base + y1 * (RDIM * 4) + g;

        uint4 q00 = __ldg(pl + r0 + x0 * 4);
        uint4 q10 = __ldg(pl + r0 + x1 * 4);
        uint4 q01 = __ldg(pl + r1 + x0 * 4);
        uint4 q11 = __ldg(pl + r1 + x1 * 4);

        float w00 = wx0 * wy0, w10 = wx1 * wy0;
        float w01 = wx0 * wy1, w11 = wx1 * wy1;

        const __half2* h00 = reinterpret_cast<const __half2*>(&q00);
        const __half2* h10 = reinterpret_cast<const __half2*>(&q10);
        const __half2* h01 = reinterpret_cast<const __half2*>(&q01);
        const __half2* h11 = reinterpret_cast<const __half2*>(&q11);

        #pragma unroll
        for (int j = 0; j < 4; j++) {
            float2 f00 = __half22float2(h00[j]);
            float2 f10 = __half22float2(h10[j]);
            float2 f01 = __half22float2(h01[j]);
            float2 f11 = __half22float2(h11[j]);
            acc[2*j]   += w00 * f00.x + w10 * f10.x + w01 * f01.x + w11 * f11.x;
            acc[2*j+1] += w00 * f00.y + w10 * f10.y + w01 * f01.y + w11 * f11.y;
        }
    }

    // Lane g writes channels [8g, 8g+8): two STG.128; warp covers full lines.
    float4* o = reinterpret_cast<float4*>(out) + pt * (CDIM / 4) + g * 2;
    o[0] = make_float4(acc[0], acc[1], acc[2], acc[3]);
    o[1] = make_float4(acc[4], acc[5], acc[6], acc[7]);
}

// ---------------------------------------------------------------------------
extern "C" void kernel_launch(void* const* d_in, const int* in_sizes, int n_in,
                              void* d_out, int out_size) {
    const float* coords   = (const float*)d_in[0];
    const float* triplane = (const float*)d_in[1];
    float*       out      = (float*)d_out;
    int M = in_sizes[0] / 3;

    transpose_clip_kernel<<<NPLANE * RDIM * (RDIM / 32), 256>>>(triplane);

    int threads = M * 4;
    sample_kernel<<<(threads + 255) / 256, 256>>>(coords, out, M);
}

// round 5
// speedup vs baseline: 1.5369x; 1.0161x over previous
#include <cuda_runtime.h>
#include <cuda_fp16.h>

#define RDIM 512
#define CDIM 32
#define NPLANE 3
#define PLANE_ELEMS (RDIM * RDIM * CDIM)   // 8,388,608 elems per plane

// 48 MB scratch: clipped triplane as fp16 in [plane][y][x][channel] layout.
// Pixel block = 32 halves = 64 B; adjacent x pixels form a contiguous 128 B span.
__device__ __half g_planes[NPLANE * PLANE_ELEMS];

// ---------------------------------------------------------------------------
// Kernel 1: transpose [p][c][y][x] -> [p][y][x][c], clip to [-1,1], fp32->fp16.
// One block = (p, y, 128-wide x tile); 256 threads.
// float4 coalesced loads; uint4 (8 x fp16) coalesced stores.
// smem xor-swizzle (col ^ 4*((c>>3)&3)) makes the column gather conflict-free.
// ---------------------------------------------------------------------------
__global__ void __launch_bounds__(256) transpose_clip_kernel(
    const float* __restrict__ src)
{
    __shared__ float tile[CDIM][128];

    int bid   = blockIdx.x;
    int xbase = (bid & 3) << 7;        // 4 x-tiles of 128
    int y     = (bid >> 2) & (RDIM - 1);
    int p     = bid >> 11;             // 4 * 512 = 2048 blocks per plane

    int t = threadIdx.x;

    // Load: 1024 float4s (32 c-rows x 32 float4s); consecutive tids ->
    // consecutive 16B within a c-row -> fully coalesced 128B transactions.
    const float* s = src + (size_t)(p * CDIM) * (RDIM * RDIM) + y * RDIM + xbase;
    #pragma unroll
    for (int i = 0; i < 4; i++) {
        int idx = t + i * 256;
        int c   = idx >> 5;
        int xq  = idx & 31;                       // float4 within row
        float4 f = __ldg(reinterpret_cast<const float4*>(s + c * (RDIM * RDIM)) + xq);
        int col = (xq * 4) ^ (4 * ((c >> 3) & 3));  // xor swizzle (16B aligned)
        *reinterpret_cast<float4*>(&tile[c][col]) = f;
    }
    __syncthreads();

    // Store: 512 uint4s (128 pixels x 4 channel-groups of 8).
    // Lane groups of 4 share x, vary cq -> swizzle gives distinct banks.
    __half* d = g_planes + ((size_t)(p * RDIM + y) * RDIM + xbase) * CDIM;
    #pragma unroll
    for (int i = 0; i < 2; i++) {
        int idx = t + i * 256;
        int x   = idx >> 2;            // pixel within tile
        int cq  = idx & 3;             // 8-channel group
        __half h[8];
        #pragma unroll
        for (int k = 0; k < 8; k++) {
            int c = cq * 8 + k;
            float v = tile[c][x ^ (4 * cq)];   // (c>>3)&3 == cq
            v = fminf(fmaxf(v, -1.0f), 1.0f);
            h[k] = __float2half_rn(v);
        }
        // consecutive idx -> consecutive 16B -> fully coalesced
        reinterpret_cast<uint4*>(d)[idx] = *reinterpret_cast<uint4*>(h);
    }
}

// ---------------------------------------------------------------------------
// Kernel 2: bilinear sampling, 8 lanes per point.
//   g & 3  -> 16B channel slice (8 fp16 channels)
//   g >> 2 -> which x-tap (x0 or x1)
// One LDG.128 per (plane,row) gathers BOTH x-taps of the row across lanes;
// x0/x1 pixel blocks are contiguous 128 B -> 1 line when x0 even, 2 when odd
// (avg 1.5) => 9 L1 wavefronts/point instead of 12.
// Plane (u=col, v=row) from inv(PLANE_AXES): p0:(cy,cx) p1:(cz,cx) p2:(cy,cz)
// ---------------------------------------------------------------------------
__global__ void __launch_bounds__(256) sample_kernel(
    const float* __restrict__ coords, float* __restrict__ out, int M)
{
    int tid = blockIdx.x * blockDim.x + threadIdx.x;
    int pt  = tid >> 3;
    if (pt >= M) return;
    int g   = tid & 7;
    int c8  = g & 3;                   // channel slice
    int xs  = g >> 2;                  // x-tap select

    float cx = __ldg(coords + pt * 3 + 0);
    float cy = __ldg(coords + pt * 3 + 1);
    float cz = __ldg(coords + pt * 3 + 2);

    const uint4* pl = reinterpret_cast<const uint4*>(g_planes);

    float u[3] = {cy, cz, cy};   // -> x (column)
    float v[3] = {cx, cx, cz};   // -> y (row)

    float acc[8];
    #pragma unroll
    for (int k = 0; k < 8; k++) acc[k] = 0.0f;

    #pragma unroll
    for (int p = 0; p < NPLANE; p++) {
        float sx = (u[p] + 1.0f) * (0.5f * (RDIM - 1));  // align_corners=True
        float sy = (v[p] + 1.0f) * (0.5f * (RDIM - 1));
        float fx = floorf(sx), fy = floorf(sy);
        int   x0 = (int)fx,    y0 = (int)fy;
        float wx1 = sx - fx,   wy1 = sy - fy;

        x0 = max(min(x0, RDIM - 1), 0);
        y0 = max(min(y0, RDIM - 1), 0);
        int x1 = min(x0 + 1, RDIM - 1);
        int y1 = min(y0 + 1, RDIM - 1);

        int   xt = xs ? x1  : x0;
        float wx = xs ? wx1 : (1.0f - wx1);
        float w0 = wx * (1.0f - wy1);
        float w1 = wx * wy1;

        int rbase = p * (RDIM * RDIM * 4) + xt * 4 + c8;   // uint4 units
        uint4 q0 = __ldg(pl + rbase + y0 * (RDIM * 4));
        uint4 q1 = __ldg(pl + rbase + y1 * (RDIM * 4));

        const __half2* h0 = reinterpret_cast<const __half2*>(&q0);
        const __half2* h1 = reinterpret_cast<const __half2*>(&q1);
        #pragma unroll
        for (int j = 0; j < 4; j++) {
            float2 f0 = __half22float2(h0[j]);
            float2 f1 = __half22float2(h1[j]);
            acc[2*j]   += w0 * f0.x + w1 * f1.x;
            acc[2*j+1] += w0 * f0.y + w1 * f1.y;
        }
    }

    // Combine x0-tap and x1-tap partial sums (partner lane = g ^ 4).
    #pragma unroll
    for (int k = 0; k < 8; k++)
        acc[k] += __shfl_xor_sync(0xffffffffu, acc[k], 4);

    // Lane writes channels [8*c8 + 4*xs, +4): warp covers 4 full output rows.
    float4 o = make_float4(acc[4*xs], acc[4*xs+1], acc[4*xs+2], acc[4*xs+3]);
    reinterpret_cast<float4*>(out)[pt * (CDIM / 4) + c8 * 2 + xs] = o;
}

// ---------------------------------------------------------------------------
extern "C" void kernel_launch(void* const* d_in, const int* in_sizes, int n_in,
                              void* d_out, int out_size) {
    const float* coords   = (const float*)d_in[0];
    const float* triplane = (const float*)d_in[1];
    float*       out      = (float*)d_out;
    int M = in_sizes[0] / 3;

    transpose_clip_kernel<<<NPLANE * RDIM * (RDIM / 128), 256>>>(triplane);

    long long threads = (long long)M * 8;
    sample_kernel<<<(int)((threads + 255) / 256), 256>>>(coords, out, M);
}

// round 6
// speedup vs baseline: 1.6489x; 1.0729x over previous
#include <cuda_runtime.h>
#include <cuda_fp16.h>

#define RDIM 512
#define CDIM 32
#define NPLANE 3
#define PLANE_ELEMS (RDIM * RDIM * CDIM)   // 8,388,608 elems per plane

// 48 MB scratch: clipped triplane as fp16 in [plane][y][x][channel] layout.
// Pixel block = 32 halves = 64 B.
__device__ __half g_planes[NPLANE * PLANE_ELEMS];

// Blackwell packed-f32x2 helpers (ptxas won't auto-fuse these from C++).
#define PACK_F32X2(out, lo, hi) \
    asm("mov.b64 %0, {%1, %2};" : "=l"(out) : "f"(lo), "f"(hi))
#define UNPACK_F32X2(lo, hi, in) \
    asm("mov.b64 {%0, %1}, %2;" : "=f"(lo), "=f"(hi) : "l"(in))
#define ADD_F32X2(out, a, b) \
    asm("add.rn.f32x2 %0, %1, %2;" : "=l"(out) : "l"(a), "l"(b))

// ---------------------------------------------------------------------------
// Kernel 1: transpose [p][c][y][x] -> [p][y][x][c], clip to [-1,1], fp32->fp16.
// One block = (p, y, 128-wide x tile); 256 threads.
// float4 coalesced loads; uint4 (8 x fp16) coalesced stores.
// smem xor-swizzle (col ^ 4*((c>>3)&3)) makes the column gather conflict-free.
// ---------------------------------------------------------------------------
__global__ void __launch_bounds__(256) transpose_clip_kernel(
    const float* __restrict__ src)
{
    __shared__ float tile[CDIM][128];

    int bid   = blockIdx.x;
    int xbase = (bid & 3) << 7;        // 4 x-tiles of 128
    int y     = (bid >> 2) & (RDIM - 1);
    int p     = bid >> 11;             // 4 * 512 = 2048 blocks per plane

    int t = threadIdx.x;

    const float* s = src + (size_t)(p * CDIM) * (RDIM * RDIM) + y * RDIM + xbase;
    #pragma unroll
    for (int i = 0; i < 4; i++) {
        int idx = t + i * 256;
        int c   = idx >> 5;
        int xq  = idx & 31;                       // float4 within row
        float4 f = __ldg(reinterpret_cast<const float4*>(s + c * (RDIM * RDIM)) + xq);
        int col = (xq * 4) ^ (4 * ((c >> 3) & 3));  // xor swizzle (16B aligned)
        *reinterpret_cast<float4*>(&tile[c][col]) = f;
    }
    __syncthreads();

    __half* d = g_planes + ((size_t)(p * RDIM + y) * RDIM + xbase) * CDIM;
    #pragma unroll
    for (int i = 0; i < 2; i++) {
        int idx = t + i * 256;
        int x   = idx >> 2;            // pixel within tile
        int cq  = idx & 3;             // 8-channel group
        __half h[8];
        #pragma unroll
        for (int k = 0; k < 8; k++) {
            int c = cq * 8 + k;
            float v = tile[c][x ^ (4 * cq)];   // (c>>3)&3 == cq
            v = fminf(fmaxf(v, -1.0f), 1.0f);
            h[k] = __float2half_rn(v);
        }
        reinterpret_cast<uint4*>(d)[idx] = *reinterpret_cast<uint4*>(h);
    }
}

// ---------------------------------------------------------------------------
// Kernel 2: bilinear sampling, 4 lanes per point (R2 layout).
// Lane g owns 8 fp16 channels (one 16B slice); 4 tap loads per plane per lane.
// Tap combine in fp16 (HFMA2, 4 slots per half2 vs 12 for fp32+convert),
// per-plane result converted once to fp32 and accumulated with add.rn.f32x2.
// Plane (u=col, v=row) from inv(PLANE_AXES): p0:(cy,cx) p1:(cz,cx) p2:(cy,cz)
// ---------------------------------------------------------------------------
__global__ void __launch_bounds__(256, 6) sample_kernel(
    const float* __restrict__ coords, float* __restrict__ out, int M)
{
    int tid = blockIdx.x * blockDim.x + threadIdx.x;
    int pt  = tid >> 2;
    if (pt >= M) return;
    int g   = tid & 3;

    float cx = __ldg(coords + pt * 3 + 0);
    float cy = __ldg(coords + pt * 3 + 1);
    float cz = __ldg(coords + pt * 3 + 2);

    const uint4* pl = reinterpret_cast<const uint4*>(g_planes);

    float u[3] = {cy, cz, cy};   // -> x (column)
    float v[3] = {cx, cx, cz};   // -> y (row)

    unsigned long long acc[4];   // 4 packed f32x2 = 8 fp32 channels
    #pragma unroll
    for (int j = 0; j < 4; j++) acc[j] = 0ULL;   // bits of (+0.f, +0.f)

    #pragma unroll
    for (int p = 0; p < NPLANE; p++) {
        // align_corners=True: sx = (u+1)*0.5*(R-1) = u*255.5 + 255.5, in [0,511)
        float sx = fmaf(u[p], 255.5f, 255.5f);
        float sy = fmaf(v[p], 255.5f, 255.5f);
        int x0 = min((int)sx, RDIM - 2);   // trunc == floor (sx >= 0)
        int y0 = min((int)sy, RDIM - 2);   // x1=x0+1, y1=y0+1 in-bounds
        float wx1 = sx - (float)x0;
        float wy1 = sy - (float)y0;
        float wx0 = 1.0f - wx1, wy0 = 1.0f - wy1;

        __half2 W00 = __float2half2_rn(wx0 * wy0);
        __half2 W10 = __float2half2_rn(wx1 * wy0);
        __half2 W01 = __float2half2_rn(wx0 * wy1);
        __half2 W11 = __float2half2_rn(wx1 * wy1);

        const uint4* r = pl + p * (RDIM * RDIM * 4) + y0 * (RDIM * 4) + x0 * 4 + g;
        uint4 q00 = __ldg(r);
        uint4 q10 = __ldg(r + 4);              // x0+1
        uint4 q01 = __ldg(r + RDIM * 4);       // y0+1
        uint4 q11 = __ldg(r + RDIM * 4 + 4);

        const __half2* h00 = reinterpret_cast<const __half2*>(&q00);
        const __half2* h10 = reinterpret_cast<const __half2*>(&q10);
        const __half2* h01 = reinterpret_cast<const __half2*>(&q01);
        const __half2* h11 = reinterpret_cast<const __half2*>(&q11);

        #pragma unroll
        for (int j = 0; j < 4; j++) {
            __half2 s = __hmul2(W00, h00[j]);
            s = __hfma2(W10, h10[j], s);
            s = __hfma2(W01, h01[j], s);
            s = __hfma2(W11, h11[j], s);
            float2 f = __half22float2(s);      // fp32 across planes
            unsigned long long pf;
            PACK_F32X2(pf, f.x, f.y);
            ADD_F32X2(acc[j], acc[j], pf);
        }
    }

    float a0, a1, a2, a3, a4, a5, a6, a7;
    UNPACK_F32X2(a0, a1, acc[0]);
    UNPACK_F32X2(a2, a3, acc[1]);
    UNPACK_F32X2(a4, a5, acc[2]);
    UNPACK_F32X2(a6, a7, acc[3]);

    // Lane g writes channels [8g, 8g+8): two STG.128; warp covers full lines.
    float4* o = reinterpret_cast<float4*>(out) + pt * (CDIM / 4) + g * 2;
    o[0] = make_float4(a0, a1, a2, a3);
    o[1] = make_float4(a4, a5, a6, a7);
}

// ---------------------------------------------------------------------------
extern "C" void kernel_launch(void* const* d_in, const int* in_sizes, int n_in,
                              void* d_out, int out_size) {
    const float* coords   = (const float*)d_in[0];
    const float* triplane = (const float*)d_in[1];
    float*       out      = (float*)d_out;
    int M = in_sizes[0] / 3;

    transpose_clip_kernel<<<NPLANE * RDIM * (RDIM / 128), 256>>>(triplane);

    long long threads = (long long)M * 4;
    sample_kernel<<<(int)((threads + 255) / 256), 256>>>(coords, out, M);
}